// round 9
// baseline (speedup 1.0000x reference)
#include <cuda_runtime.h>
#include <math.h>

#define KK 769
#define MM 384
#define BB 64
#define LL 256
#define AA 21
#define ESTR 772
#define NEGV (-1.0e32f)

__device__ __align__(16) float g_eobs[(AA + 1) * ESTR];
__device__ float g_cm[KK];
__device__ float g_ci[KK];
__device__ float g_cf[KK];
__device__ float g_et[KK];
__device__ float g_w[MM];
__device__ float g_einit[KK];

// ---------------- emission table (parallel, independent of prep) ----------------
__global__ __launch_bounds__(128) void emis_kernel(
    const float* __restrict__ pre, const float* __restrict__ iseq)
{
    const int k = blockIdx.x * 128 + threadIdx.x;
    if (k >= KK) return;
    const float* row = (k < MM) ? (pre + k * AA) : (iseq + (k - MM) * AA);
    float mx = -INFINITY;
    #pragma unroll
    for (int a = 0; a < AA; a++) mx = fmaxf(mx, row[a]);
    float sm = 0.f;
    #pragma unroll
    for (int a = 0; a < AA; a++) sm += __expf(row[a] - mx);
    float l = mx + __logf(sm);
    float sm2 = 0.f;
    #pragma unroll
    for (int a = 0; a < AA; a++) sm2 += __expf(row[a] - l);
    float nrm = l + __logf(sm2);
    #pragma unroll
    for (int a = 0; a < AA; a++) g_eobs[a * ESTR + k] = __expf(row[a] - nrm);
    g_eobs[AA * ESTR + k] = 1.0f;
}

// ---------------- prep: transition constants + init ----------------
__global__ __launch_bounds__(512) void prep_kernel(
    const float* __restrict__ ins, const float* __restrict__ del)
{
    __shared__ float lre[(MM + 1) * 6], lue[(MM + 1) * 6];
    __shared__ float sC[MM + 2], sW2[MM + 1], sQt[MM + 1], sG[MM + 1];
    __shared__ float WT[16], ST[16], FIN[16], red[16];
    __shared__ float sInit[KK];

    const int tid = threadIdx.x, lane = tid & 31, wid = tid >> 5;

    for (int idx = tid; idx < MM * 3; idx += 512) {
        float x0 = ins[idx * 2], x1 = ins[idx * 2 + 1];
        float mx = fmaxf(x0, x1);
        float l = mx + __logf(__expf(x0 - mx) + __expf(x1 - mx));
        lre[idx * 2] = x0 - l; lre[idx * 2 + 1] = x1 - l;
        x0 = del[idx * 2]; x1 = del[idx * 2 + 1];
        mx = fmaxf(x0, x1);
        l = mx + __logf(__expf(x0 - mx) + __expf(x1 - mx));
        lue[idx * 2] = x0 - l; lue[idx * 2 + 1] = x1 - l;
    }
    if (tid < 3) {
        lre[(MM * 3 + tid) * 2 + 0] = NEGV; lre[(MM * 3 + tid) * 2 + 1] = 0.f;
        lue[(MM * 3 + tid) * 2 + 0] = 0.f;  lue[(MM * 3 + tid) * 2 + 1] = NEGV;
    }
    __syncthreads();

    { // C (exclusive cumsum of d2), w2, Qt
        float d2 = 0.f;
        if (tid < MM) d2 = lre[(tid * 3 + 2) * 2 + 0] + lue[(tid * 3 + 2) * 2 + 1];
        float inc = d2;
        #pragma unroll
        for (int o = 1; o < 32; o <<= 1) {
            float t = __shfl_up_sync(0xffffffffu, inc, o);
            if (lane >= o) inc += t;
        }
        if (lane == 31) WT[wid] = inc;
        __syncthreads();
        float off = 0.f;
        for (int j = 0; j < wid; j++) off += WT[j];
        if (tid < MM) { sC[tid + 1] = inc + off; sW2[tid] = __expf(d2); }
        if (tid == 0) { sC[0] = 0.f; sC[MM + 1] = 0.f; sW2[MM] = 0.f; }
        if (tid <= MM) {
            float q = __expf(lre[(tid * 3 + 2) * 2 + 1]);
            if (tid < MM) q += __expf(lre[(tid * 3 + 2) * 2 + 0] + lue[(tid * 3 + 2) * 2 + 0]);
            sQt[tid] = q;
        }
        __syncthreads();
    }
    { // G via reverse affine scan
        float A = 1.f, Bv = 0.f;
        if (tid < MM) { A = sW2[MM - tid]; Bv = sQt[MM - tid]; }
        #pragma unroll
        for (int o = 1; o < 32; o <<= 1) {
            float Wp = __shfl_up_sync(0xffffffffu, A, o);
            float Sp = __shfl_up_sync(0xffffffffu, Bv, o);
            if (lane >= o) { Bv = fmaf(A, Sp, Bv); A *= Wp; }
        }
        if (lane == 31 && wid < 12) { WT[wid] = A; ST[wid] = Bv; }
        __syncthreads();
        if (wid == 0) {
            float Wt = (lane < 12) ? WT[lane] : 1.f;
            float St = (lane < 12) ? ST[lane] : 0.f;
            #pragma unroll
            for (int o = 1; o < 16; o <<= 1) {
                float Wp = __shfl_up_sync(0xffffffffu, Wt, o);
                float Sp = __shfl_up_sync(0xffffffffu, St, o);
                if (lane >= o) { St = fmaf(Wt, Sp, St); Wt *= Wp; }
            }
            float e = __shfl_up_sync(0xffffffffu, St, 1);
            if (lane == 0) e = 0.f;
            if (lane < 12) FIN[lane] = e;
        }
        __syncthreads();
        if (tid < MM) sG[MM - 1 - tid] = fmaf(A, FIN[wid], Bv);
        if (tid == 0) sG[MM] = 0.f;
        __syncthreads();
    }
    for (int k = tid; k < KK; k += 512) {
        const int m = (k < MM) ? k : k - MM;
        const int g = (k < MM) ? 0 : 1;
        const int s = m + 1 - g;
        float src_stay  = lre[(s * 3 + g) * 2 + 0];
        float src_ins   = lre[(s * 3 + g) * 2 + 1];
        float src_match = lue[(s * 3 + g) * 2 + 0];
        float src_del   = lue[(s * 3 + g) * 2 + 1];
        float dmatch = src_stay + src_match, dins = src_ins, cflog = src_stay + src_del;
        float rowsum = __expf(dins) + ((s < MM) ? __expf(dmatch) : 0.f) + __expf(cflog) * sG[s];
        float lse = __logf(rowsum);
        g_cm[k] = __expf(dmatch - lse);
        g_ci[k] = __expf(dins - lse);
        g_cf[k] = __expf(cflog - lse);
        float tterm = (g == 1) ? lre[(m * 3 + 2) * 2 + 1]
                               : (lre[(m * 3 + 2) * 2 + 0] + lue[(m * 3 + 2) * 2 + 0]);
        g_et[k] = __expf(tterm);
        float initv;
        if (m == 0) initv = (g == 1) ? lre[1] : (lre[0] + lue[0]);
        else        initv = lre[0] + lue[1] - sC[1] + sC[m] + tterm;
        sInit[k] = initv;
    }
    if (tid < MM) g_w[tid] = sW2[tid];
    __syncthreads();
    { // normalized exp(init)
        float mloc = -INFINITY;
        for (int k = tid; k < KK; k += 512) mloc = fmaxf(mloc, sInit[k]);
        #pragma unroll
        for (int o = 16; o; o >>= 1) mloc = fmaxf(mloc, __shfl_xor_sync(0xffffffffu, mloc, o));
        if (lane == 0) red[wid] = mloc;
        __syncthreads();
        float mxI = red[0];
        #pragma unroll
        for (int j = 1; j < 16; j++) mxI = fmaxf(mxI, red[j]);
        __syncthreads();
        float s0 = 0.f;
        for (int k = tid; k < KK; k += 512) s0 += __expf(sInit[k] - mxI);
        #pragma unroll
        for (int o = 16; o; o >>= 1) s0 += __shfl_xor_sync(0xffffffffu, s0, o);
        if (lane == 0) red[wid] = s0;
        __syncthreads();
        float Z = 0.f;
        for (int j = 0; j < 16; j++) Z += red[j];
        float lz = mxI + __logf(Z);
        for (int k = tid; k < KK; k += 512) g_einit[k] = __expf(sInit[k] - lz);
    }
}

// ---------------- forward: 4 warps x 3 elems, fused 2-step rounds ----------------
__global__ void __launch_bounds__(128) hmm_forward(const float* __restrict__ seq,
                                                   const float* __restrict__ lscale,
                                                   float* __restrict__ out)
{
    __shared__ float4 s_TA[4], s_TB[4];  // (W,P,Q,b1) ; (be,b2,b3,zs)
    __shared__ float4 s_bnd[4];          // (um[1],um[2],ui[2]) of prev warp; [0]=0
    __shared__ float  s_red[4];
    __shared__ int    s_let[LL];

    const int b = blockIdx.x, tid = threadIdx.x, lane = tid & 31, wid = tid >> 5;
    const int j0 = tid * 3, jP = tid ? j0 - 1 : 0;
    const bool l127 = (tid == 127);

    for (int l = tid; l < LL; l += 128) {
        const float* row = seq + ((size_t)b * LL + l) * AA;
        int let = AA;
        #pragma unroll
        for (int a = 0; a < AA; a++)
            if (row[a] > 0.5f) let = a;
        s_let[l] = let * ESTR;
    }

    float w_[3], cfa[3], cfb[3], cma[3], cmb[3], cia[3], cib[3], etm[3], eti[3];
    #pragma unroll
    for (int q = 0; q < 3; q++) {
        const int j = j0 + q;
        w_[q]  = g_w[j];
        cfa[q] = g_cf[MM + j];  cfb[q] = j ? g_cf[j - 1] : 0.f;
        cma[q] = g_cm[MM + j];  cmb[q] = j ? g_cm[j - 1] : 0.f;
        cia[q] = g_ci[MM + j];  cib[q] = j ? g_ci[j - 1] : 0.f;
        etm[q] = g_et[j];       eti[q] = g_et[MM + j];
    }
    const float etmP = tid ? g_et[jP] : 0.f;
    const float cmaP = tid ? g_cm[MM + jP] : 0.f;
    const float cmbP = (tid && jP) ? g_cm[jP - 1] : 0.f;
    float kq[3];
    kq[0] = cfb[0] * etmP; kq[1] = cfb[1] * etm[0]; kq[2] = cfb[2] * etm[1];
    float et_x = 0.f, ci_xa = 0.f, ci_xb = 0.f;
    if (l127) { et_x = g_et[KK - 1]; ci_xa = g_ci[KK - 1]; ci_xb = g_ci[MM - 1]; }

    __syncthreads();

    float um[3], ui[3], ux = 0.f;
    {
        const float* ob = g_eobs + s_let[0];
        #pragma unroll
        for (int q = 0; q < 3; q++) {
            um[q] = g_einit[j0 + q]      * ob[j0 + q];
            ui[q] = g_einit[MM + j0 + q] * ob[MM + j0 + q];
        }
        if (l127) ux = g_einit[KK - 1] * ob[KK - 1];
        if (tid == 0) s_bnd[0] = make_float4(0.f, 0.f, 0.f, 0.f);
        if (lane == 31 && wid < 3) s_bnd[wid + 1] = make_float4(um[1], um[2], ui[2], 0.f);
    }
    __syncthreads();

    int pacc = 0;

    // -------- single step (transition to t=1) --------
    {
        const float* ob1 = g_eobs + s_let[1];
        float E1m[3], E1i[3];
        #pragma unroll
        for (int q = 0; q < 3; q++) { E1m[q] = ob1[j0 + q]; E1i[q] = ob1[MM + j0 + q]; }
        float e1x = l127 ? ob1[KK - 1] : 0.f;

        float um2v = __shfl_up_sync(0xffffffffu, um[2], 1);
        if (lane == 0) um2v = s_bnd[wid].y;
        float ub[3] = { um2v, um[0], um[1] };

        float SA[3], Lm[3], Li[3];
        #pragma unroll
        for (int q = 0; q < 3; q++) {
            SA[q] = fmaf(ub[q], cfb[q], ui[q] * cfa[q]);
            Lm[q] = E1m[q] * fmaf(ub[q], cmb[q], ui[q] * cma[q]);
            Li[q] = E1i[q] * fmaf(ub[q], cib[q], ui[q] * cia[q]);
        }
        float zs = ((um[0] + um[1]) + (um[2] + ux)) + ((ui[0] + ui[1]) + ui[2]);
        float Wv = w_[0], Sv = SA[0];
        Sv = fmaf(w_[1], Sv, SA[1]); Wv *= w_[1];
        Sv = fmaf(w_[2], Sv, SA[2]); Wv *= w_[2];
        #pragma unroll
        for (int o = 1; o < 32; o <<= 1) {
            float Wp = __shfl_up_sync(0xffffffffu, Wv, o);
            float Sp = __shfl_up_sync(0xffffffffu, Sv, o);
            if (lane >= o) { Sv = fmaf(Wv, Sp, Sv); Wv *= Wp; }
        }
        #pragma unroll
        for (int o = 16; o; o >>= 1) zs += __shfl_xor_sync(0xffffffffu, zs, o);
        if (lane == 31) s_TA[wid] = make_float4(Wv, Sv, zs, 0.f);
        __syncthreads();

        float4 T0 = s_TA[0], T1 = s_TA[1], T2 = s_TA[2], T3 = s_TA[3];
        float Tz = (T0.z + T1.z) + (T2.z + T3.z);
        unsigned ze = (__float_as_uint(Tz) >> 23) & 255u;
        pacc += (int)ze - 127;
        float rz = __uint_as_float((254u - ze) << 23);

        float fin = 0.f;
        if (wid > 0) fin = T0.y;
        if (wid > 1) fin = fmaf(T1.x, fin, T1.y);
        if (wid > 2) fin = fmaf(T2.x, fin, T2.y);
        float Wp = __shfl_up_sync(0xffffffffu, Wv, 1);
        float Sp = __shfl_up_sync(0xffffffffu, Sv, 1);
        float F = lane ? fmaf(Wp, fin, Sp) : fin;

        float um2old = um[2], uxold = ux;
        #pragma unroll
        for (int q = 0; q < 3; q++) {
            um[q] = fmaf(E1m[q] * etm[q], F, Lm[q]) * rz;
            ui[q] = fmaf(E1i[q] * eti[q], F, Li[q]) * rz;
            F = fmaf(w_[q], F, SA[q]);
        }
        if (l127)
            ux = e1x * fmaf(et_x, F, fmaf(uxold, ci_xa, um2old * ci_xb)) * rz;
        if (lane == 31 && wid < 3) s_bnd[wid + 1] = make_float4(um[1], um[2], ui[2], 0.f);
        __syncthreads();
    }

    // -------- 127 fused rounds (transitions t, t+1) --------
    for (int t = 2; t < LL; t += 2) {
        const float* ob1 = g_eobs + s_let[t];
        const float* ob2 = g_eobs + s_let[t + 1];
        float E1m[3], E1i[3], E2m[3], E2i[3];
        #pragma unroll
        for (int q = 0; q < 3; q++) {
            E1m[q] = ob1[j0 + q]; E1i[q] = ob1[MM + j0 + q];
            E2m[q] = ob2[j0 + q]; E2i[q] = ob2[MM + j0 + q];
        }
        const float E1mP = ob1[jP];
        float e1x = 0.f, e2x = 0.f;
        if (l127) { e1x = ob1[KK - 1]; e2x = ob2[KK - 1]; }

        float um1v = __shfl_up_sync(0xffffffffu, um[1], 1);
        float um2v = __shfl_up_sync(0xffffffffu, um[2], 1);
        float ui2v = __shfl_up_sync(0xffffffffu, ui[2], 1);
        if (lane == 0) { float4 bd = s_bnd[wid]; um1v = bd.x; um2v = bd.y; ui2v = bd.z; }
        float ub[3] = { um2v, um[0], um[1] };

        float SA[3], Lm[3], Li[3], pm[3], pe[3], pF[3], qc[3], r[3];
        #pragma unroll
        for (int q = 0; q < 3; q++) {
            SA[q] = fmaf(ub[q], cfb[q], ui[q] * cfa[q]);
            Lm[q] = E1m[q] * fmaf(ub[q], cmb[q], ui[q] * cma[q]);
            Li[q] = E1i[q] * fmaf(ub[q], cib[q], ui[q] * cia[q]);
            pm[q] = E1m[q] * etm[q];
            pe[q] = E1i[q] * eti[q];
            pF[q] = cfa[q] * pe[q];
        }
        qc[0] = kq[0] * E1mP; qc[1] = kq[1] * E1m[0]; qc[2] = kq[2] * E1m[1];
        const float pmP = E1mP * etmP;
        const float LmP = E1mP * fmaf(um1v, cmbP, ui2v * cmaP);
        r[0] = fmaf(cfa[0], Li[0], cfb[0] * LmP);
        r[1] = fmaf(cfa[1], Li[1], cfb[1] * Lm[0]);
        r[2] = fmaf(cfa[2], Li[2], cfb[2] * Lm[1]);

        float zs = ((um[0] + um[1]) + (um[2] + ux)) + ((ui[0] + ui[1]) + ui[2]);

        // serial compose of 3 per-element maps (7-var family, al==W)
        float W = w_[0], P = pF[0], Q = qc[0], be = 1.f;
        float b1 = r[0], b2 = SA[0], b3 = 0.f;
        #pragma unroll
        for (int q = 1; q < 3; q++) {
            float nW = w_[q] * W;
            float nP = fmaf(w_[q], P, fmaf(pF[q], W, qc[q] * be));
            float nQ = w_[q] * Q;
            float nbe = W;
            float nb1 = fmaf(w_[q], b1, fmaf(pF[q], b2, fmaf(qc[q], b3, r[q])));
            float nb2 = fmaf(w_[q], b2, SA[q]);
            float nb3 = b2;
            W = nW; P = nP; Q = nQ; be = nbe; b1 = nb1; b2 = nb2; b3 = nb3;
        }
        // 7-var inclusive warp scan
        #pragma unroll
        for (int o = 1; o < 32; o <<= 1) {
            float Wp = __shfl_up_sync(0xffffffffu, W, o);
            float Pp = __shfl_up_sync(0xffffffffu, P, o);
            float Qp = __shfl_up_sync(0xffffffffu, Q, o);
            float bep = __shfl_up_sync(0xffffffffu, be, o);
            float b1p = __shfl_up_sync(0xffffffffu, b1, o);
            float b2p = __shfl_up_sync(0xffffffffu, b2, o);
            float b3p = __shfl_up_sync(0xffffffffu, b3, o);
            if (lane >= o) {
                float nP = fmaf(W, Pp, fmaf(P, Wp, Q * bep));
                float nb1 = fmaf(W, b1p, fmaf(P, b2p, fmaf(Q, b3p, b1)));
                float nb2 = fmaf(W, b2p, b2);
                float nb3 = fmaf(be, b2p, b3);
                be = be * Wp; Q = W * Qp; W = W * Wp;
                P = nP; b1 = nb1; b2 = nb2; b3 = nb3;
            }
        }
        #pragma unroll
        for (int o = 16; o; o >>= 1) zs += __shfl_xor_sync(0xffffffffu, zs, o);
        if (lane == 31) {
            s_TA[wid] = make_float4(W, P, Q, b1);
            s_TB[wid] = make_float4(be, b2, b3, zs);
        }
        __syncthreads();

        float rz;
        {
            float Tz = (s_TB[0].w + s_TB[1].w) + (s_TB[2].w + s_TB[3].w);
            unsigned ze = (__float_as_uint(Tz) >> 23) & 255u;
            pacc += (int)ze - 127;
            rz = __uint_as_float((254u - ze) << 23);
        }
        float f1 = 0.f, f2 = 0.f, f3 = 0.f;
        if (wid > 0) { f1 = s_TA[0].w; f2 = s_TB[0].y; f3 = s_TB[0].z; }
        #pragma unroll
        for (int wq = 1; wq < 3; wq++) {
            if (wid > wq) {
                float4 A = s_TA[wq], Bv = s_TB[wq];
                float nf3 = fmaf(Bv.x, f2, Bv.z);
                float nf1 = fmaf(A.x, f1, fmaf(A.y, f2, fmaf(A.z, f3, A.w)));
                float nf2 = fmaf(A.x, f2, Bv.y);
                f1 = nf1; f2 = nf2; f3 = nf3;
            }
        }
        float Wp = __shfl_up_sync(0xffffffffu, W, 1);
        float Pp = __shfl_up_sync(0xffffffffu, P, 1);
        float Qp = __shfl_up_sync(0xffffffffu, Q, 1);
        float bep = __shfl_up_sync(0xffffffffu, be, 1);
        float b1p = __shfl_up_sync(0xffffffffu, b1, 1);
        float b2p = __shfl_up_sync(0xffffffffu, b2, 1);
        float b3p = __shfl_up_sync(0xffffffffu, b3, 1);
        float FB, FA, FAp;
        if (lane) {
            FB  = fmaf(Wp, f1, fmaf(Pp, f2, fmaf(Qp, f3, b1p)));
            FA  = fmaf(Wp, f2, b2p);
            FAp = fmaf(bep, f2, b3p);
        } else { FB = f1; FA = f2; FAp = f3; }

        float vmprev = fmaf(pmP, FAp, LmP);
        float um2old = um[2], uxold = ux;
        #pragma unroll
        for (int q = 0; q < 3; q++) {
            float vi = fmaf(pe[q], FA, Li[q]);
            float zm = E2m[q] * fmaf(etm[q], FB, fmaf(vi, cma[q], vmprev * cmb[q]));
            float zi = E2i[q] * fmaf(eti[q], FB, fmaf(vi, cia[q], vmprev * cib[q]));
            float vm = fmaf(pm[q], FA, Lm[q]);
            float SB = fmaf(pF[q], FA, fmaf(qc[q], FAp, r[q]));
            float FBn = fmaf(w_[q], FB, SB);
            FAp = FA; FA = fmaf(w_[q], FA, SA[q]); FB = FBn; vmprev = vm;
            um[q] = zm * rz; ui[q] = zi * rz;
        }
        if (l127) {
            float vx = e1x * fmaf(et_x, FA, fmaf(uxold, ci_xa, um2old * ci_xb));
            ux = e2x * fmaf(et_x, FB, fmaf(vx, ci_xa, vmprev * ci_xb)) * rz;
        }
        if (lane == 31 && wid < 3) s_bnd[wid + 1] = make_float4(um[1], um[2], ui[2], 0.f);
        __syncthreads();
    }

    // -------- final: log(sum u) + 2^pacc --------
    float ps = ((um[0] + um[1]) + (um[2] + ux)) + ((ui[0] + ui[1]) + ui[2]);
    #pragma unroll
    for (int o = 16; o; o >>= 1) ps += __shfl_xor_sync(0xffffffffu, ps, o);
    if (lane == 0) s_red[wid] = ps;
    __syncthreads();
    if (tid == 0) {
        float Zt = (s_red[0] + s_red[1]) + (s_red[2] + s_red[3]);
        out[b] = lscale[0] * ((float)((double)pacc * 0.6931471805599453) + __logf(Zt));
    }
}

extern "C" void kernel_launch(void* const* d_in, const int* in_sizes, int n_in,
                              void* d_out, int out_size)
{
    const float* pre  = (const float*)d_in[0];
    const float* iseq = (const float*)d_in[1];
    const float* ins  = (const float*)d_in[2];
    const float* del  = (const float*)d_in[3];
    const float* seq  = (const float*)d_in[4];
    const float* ls   = (const float*)d_in[5];
    float* out = (float*)d_out;

    prep_kernel<<<1, 512>>>(ins, del);
    emis_kernel<<<7, 128>>>(pre, iseq);
    hmm_forward<<<BB, 128>>>(seq, ls, out);
}

// round 10
// speedup vs baseline: 1.3959x; 1.3959x over previous
#include <cuda_runtime.h>
#include <math.h>

#define KK 769
#define MM 384
#define BB 64
#define LL 256
#define AA 21
#define ESTR 772
#define NEGV (-1.0e32f)

__device__ __align__(16) float g_eobs[(AA + 1) * ESTR];
__device__ float g_cm[KK];
__device__ float g_ci[KK];
__device__ float g_cf[KK];
__device__ float g_et[KK];
__device__ float g_w[MM];
__device__ float g_einit[KK];

// ---------------- emission table (parallel, independent of prep) ----------------
__global__ __launch_bounds__(128) void emis_kernel(
    const float* __restrict__ pre, const float* __restrict__ iseq)
{
    const int k = blockIdx.x * 128 + threadIdx.x;
    if (k >= KK) return;
    const float* row = (k < MM) ? (pre + k * AA) : (iseq + (k - MM) * AA);
    float mx = -INFINITY;
    #pragma unroll
    for (int a = 0; a < AA; a++) mx = fmaxf(mx, row[a]);
    float sm = 0.f;
    #pragma unroll
    for (int a = 0; a < AA; a++) sm += __expf(row[a] - mx);
    float l = mx + __logf(sm);
    float sm2 = 0.f;
    #pragma unroll
    for (int a = 0; a < AA; a++) sm2 += __expf(row[a] - l);
    float nrm = l + __logf(sm2);
    #pragma unroll
    for (int a = 0; a < AA; a++) g_eobs[a * ESTR + k] = __expf(row[a] - nrm);
    g_eobs[AA * ESTR + k] = 1.0f;
}

// ---------------- prep: transition constants + init ----------------
__global__ __launch_bounds__(512) void prep_kernel(
    const float* __restrict__ ins, const float* __restrict__ del)
{
    __shared__ float lre[(MM + 1) * 6], lue[(MM + 1) * 6];
    __shared__ float sC[MM + 2], sW2[MM + 1], sQt[MM + 1], sG[MM + 1];
    __shared__ float WT[16], ST[16], FIN[16], red[16];
    __shared__ float sInit[KK];

    const int tid = threadIdx.x, lane = tid & 31, wid = tid >> 5;

    for (int idx = tid; idx < MM * 3; idx += 512) {
        float x0 = ins[idx * 2], x1 = ins[idx * 2 + 1];
        float mx = fmaxf(x0, x1);
        float l = mx + __logf(__expf(x0 - mx) + __expf(x1 - mx));
        lre[idx * 2] = x0 - l; lre[idx * 2 + 1] = x1 - l;
        x0 = del[idx * 2]; x1 = del[idx * 2 + 1];
        mx = fmaxf(x0, x1);
        l = mx + __logf(__expf(x0 - mx) + __expf(x1 - mx));
        lue[idx * 2] = x0 - l; lue[idx * 2 + 1] = x1 - l;
    }
    if (tid < 3) {
        lre[(MM * 3 + tid) * 2 + 0] = NEGV; lre[(MM * 3 + tid) * 2 + 1] = 0.f;
        lue[(MM * 3 + tid) * 2 + 0] = 0.f;  lue[(MM * 3 + tid) * 2 + 1] = NEGV;
    }
    __syncthreads();

    { // C (exclusive cumsum of d2), w2, Qt
        float d2 = 0.f;
        if (tid < MM) d2 = lre[(tid * 3 + 2) * 2 + 0] + lue[(tid * 3 + 2) * 2 + 1];
        float inc = d2;
        #pragma unroll
        for (int o = 1; o < 32; o <<= 1) {
            float t = __shfl_up_sync(0xffffffffu, inc, o);
            if (lane >= o) inc += t;
        }
        if (lane == 31) WT[wid] = inc;
        __syncthreads();
        float off = 0.f;
        for (int j = 0; j < wid; j++) off += WT[j];
        if (tid < MM) { sC[tid + 1] = inc + off; sW2[tid] = __expf(d2); }
        if (tid == 0) { sC[0] = 0.f; sC[MM + 1] = 0.f; sW2[MM] = 0.f; }
        if (tid <= MM) {
            float q = __expf(lre[(tid * 3 + 2) * 2 + 1]);
            if (tid < MM) q += __expf(lre[(tid * 3 + 2) * 2 + 0] + lue[(tid * 3 + 2) * 2 + 0]);
            sQt[tid] = q;
        }
        __syncthreads();
    }
    { // G via reverse affine scan
        float A = 1.f, Bv = 0.f;
        if (tid < MM) { A = sW2[MM - tid]; Bv = sQt[MM - tid]; }
        #pragma unroll
        for (int o = 1; o < 32; o <<= 1) {
            float Wp = __shfl_up_sync(0xffffffffu, A, o);
            float Sp = __shfl_up_sync(0xffffffffu, Bv, o);
            if (lane >= o) { Bv = fmaf(A, Sp, Bv); A *= Wp; }
        }
        if (lane == 31 && wid < 12) { WT[wid] = A; ST[wid] = Bv; }
        __syncthreads();
        if (wid == 0) {
            float Wt = (lane < 12) ? WT[lane] : 1.f;
            float St = (lane < 12) ? ST[lane] : 0.f;
            #pragma unroll
            for (int o = 1; o < 16; o <<= 1) {
                float Wp = __shfl_up_sync(0xffffffffu, Wt, o);
                float Sp = __shfl_up_sync(0xffffffffu, St, o);
                if (lane >= o) { St = fmaf(Wt, Sp, St); Wt *= Wp; }
            }
            float e = __shfl_up_sync(0xffffffffu, St, 1);
            if (lane == 0) e = 0.f;
            if (lane < 12) FIN[lane] = e;
        }
        __syncthreads();
        if (tid < MM) sG[MM - 1 - tid] = fmaf(A, FIN[wid], Bv);
        if (tid == 0) sG[MM] = 0.f;
        __syncthreads();
    }
    for (int k = tid; k < KK; k += 512) {
        const int m = (k < MM) ? k : k - MM;
        const int g = (k < MM) ? 0 : 1;
        const int s = m + 1 - g;
        float src_stay  = lre[(s * 3 + g) * 2 + 0];
        float src_ins   = lre[(s * 3 + g) * 2 + 1];
        float src_match = lue[(s * 3 + g) * 2 + 0];
        float src_del   = lue[(s * 3 + g) * 2 + 1];
        float dmatch = src_stay + src_match, dins = src_ins, cflog = src_stay + src_del;
        float rowsum = __expf(dins) + ((s < MM) ? __expf(dmatch) : 0.f) + __expf(cflog) * sG[s];
        float lse = __logf(rowsum);
        g_cm[k] = __expf(dmatch - lse);
        g_ci[k] = __expf(dins - lse);
        g_cf[k] = __expf(cflog - lse);
        float tterm = (g == 1) ? lre[(m * 3 + 2) * 2 + 1]
                               : (lre[(m * 3 + 2) * 2 + 0] + lue[(m * 3 + 2) * 2 + 0]);
        g_et[k] = __expf(tterm);
        float initv;
        if (m == 0) initv = (g == 1) ? lre[1] : (lre[0] + lue[0]);
        else        initv = lre[0] + lue[1] - sC[1] + sC[m] + tterm;
        sInit[k] = initv;
    }
    if (tid < MM) g_w[tid] = sW2[tid];
    __syncthreads();
    { // normalized exp(init)
        float mloc = -INFINITY;
        for (int k = tid; k < KK; k += 512) mloc = fmaxf(mloc, sInit[k]);
        #pragma unroll
        for (int o = 16; o; o >>= 1) mloc = fmaxf(mloc, __shfl_xor_sync(0xffffffffu, mloc, o));
        if (lane == 0) red[wid] = mloc;
        __syncthreads();
        float mxI = red[0];
        #pragma unroll
        for (int j = 1; j < 16; j++) mxI = fmaxf(mxI, red[j]);
        __syncthreads();
        float s0 = 0.f;
        for (int k = tid; k < KK; k += 512) s0 += __expf(sInit[k] - mxI);
        #pragma unroll
        for (int o = 16; o; o >>= 1) s0 += __shfl_xor_sync(0xffffffffu, s0, o);
        if (lane == 0) red[wid] = s0;
        __syncthreads();
        float Z = 0.f;
        for (int j = 0; j < 16; j++) Z += red[j];
        float lz = mxI + __logf(Z);
        for (int k = tid; k < KK; k += 512) g_einit[k] = __expf(sInit[k] - lz);
    }
}

// ---------------- one forward step: constant-W scan, ONE barrier ----------------
template <bool RESC, int P>
__device__ __forceinline__ void stepfn(
    const float (&um)[3], const float (&ui)[3], float uxin,
    float (&vm)[3], float (&vi)[3], float& vx,
    const float (&w_)[3], const float (&cfa)[3], const float (&cfb)[3],
    const float (&cma)[3], const float (&cmb)[3],
    const float (&cia)[3], const float (&cib)[3],
    const float (&etm)[3], const float (&eti)[3],
    const float (&WL)[5], float Wexcl, float WT1, float WT2,
    float kw1, float kw2, float kw3,
    float2 (*s_T)[4], float4* s_bnd,
    int j0, int lane, int wid, bool l127,
    float et_x, float ci_xa, float ci_xb,
    const float* __restrict__ ob, int& pacc)
{
    // emission loads (issued early, L1/L2-resident)
    float em[3], ei[3];
    #pragma unroll
    for (int q = 0; q < 3; q++) { em[q] = ob[j0 + q]; ei[q] = ob[MM + j0 + q]; }
    float e_x = l127 ? ob[KK - 1] : 0.f;

    // intra-warp boundary (valid for lanes >= 1)
    float ubm1 = __shfl_up_sync(0xffffffffu, um[2], 1);
    float ub_s = lane ? ubm1 : 0.f;

    // sources (lane0's first source partial; its B-term injected via composition)
    float Sr[3];
    Sr[0] = fmaf(ub_s, cfb[0], ui[0] * cfa[0]);
    Sr[1] = fmaf(um[0], cfb[1], ui[1] * cfa[1]);
    Sr[2] = fmaf(um[1], cfb[2], ui[2] * cfa[2]);
    float Sv = Sr[0];
    Sv = fmaf(w_[1], Sv, Sr[1]);
    Sv = fmaf(w_[2], Sv, Sr[2]);

    // S-only inclusive affine scan (W multipliers are precomputed constants)
    #pragma unroll
    for (int k = 0; k < 5; k++) {
        const int o = 1 << k;
        float Sp = __shfl_up_sync(0xffffffffu, Sv, o);
        if (lane >= o) Sv = fmaf(WL[k], Sp, Sv);
    }

    float zs = 0.f;
    if (RESC) {
        zs = ((um[0] + um[1]) + (um[2] + uxin)) + ((ui[0] + ui[1]) + ui[2]);
        #pragma unroll
        for (int o = 16; o; o >>= 1) zs += __shfl_xor_sync(0xffffffffu, zs, o);
    }
    if (lane == 31) s_T[P][wid] = make_float2(Sv, zs);
    __syncthreads();

    // phase 2
    float2 T0 = s_T[P][0], T1 = s_T[P][1], T2 = s_T[P][2];
    float rz = 1.f;
    if (RESC) {
        float2 T3 = s_T[P][3];
        float Tz = (T0.y + T1.y) + (T2.y + T3.y);
        unsigned ze = (__float_as_uint(Tz) >> 23) & 255u;
        pacc += (int)ze - 127;
        rz = __uint_as_float((254u - ze) << 23);
    }
    float4 bv = s_bnd[P];
    float bc1 = bv.y * kw1, bc2 = bv.z * kw2, bc3 = bv.w * kw3;
    float Fin = 0.f;
    if (wid > 0) Fin = T0.x + bc1;
    if (wid > 1) Fin = fmaf(WT1, Fin, T1.x) + bc2;
    if (wid > 2) Fin = fmaf(WT2, Fin, T2.x) + bc3;

    float Sp = __shfl_up_sync(0xffffffffu, Sv, 1);
    float Fexp = lane ? fmaf(Wexcl, Fin, Sp) : Fin;
    float bc_own = (wid == 1) ? bc1 : ((wid == 2) ? bc2 : ((wid == 3) ? bc3 : 0.f));
    float ubw    = (wid == 1) ? bv.y : ((wid == 2) ? bv.z : ((wid == 3) ? bv.w : 0.f));
    float F0  = lane ? Fexp : (Fexp - bc_own);
    float ub0 = lane ? ubm1 : ubw;

    float prm = fmaf(ub0, cmb[0], fmaf(ui[0], cma[0], etm[0] * F0));
    float pri = fmaf(ub0, cib[0], fmaf(ui[0], cia[0], eti[0] * F0));
    vm[0] = RESC ? prm * em[0] * rz : prm * em[0];
    vi[0] = RESC ? pri * ei[0] * rz : pri * ei[0];
    float F = fmaf(w_[0], Fexp, Sr[0]);
    prm = fmaf(um[0], cmb[1], fmaf(ui[1], cma[1], etm[1] * F));
    pri = fmaf(um[0], cib[1], fmaf(ui[1], cia[1], eti[1] * F));
    vm[1] = RESC ? prm * em[1] * rz : prm * em[1];
    vi[1] = RESC ? pri * ei[1] * rz : pri * ei[1];
    F = fmaf(w_[1], F, Sr[1]);
    prm = fmaf(um[1], cmb[2], fmaf(ui[2], cma[2], etm[2] * F));
    pri = fmaf(um[1], cib[2], fmaf(ui[2], cia[2], eti[2] * F));
    vm[2] = RESC ? prm * em[2] * rz : prm * em[2];
    vi[2] = RESC ? pri * ei[2] * rz : pri * ei[2];
    vx = 0.f;
    if (l127) {
        F = fmaf(w_[2], F, Sr[2]);
        float prx = fmaf(et_x, F, fmaf(um[2], ci_xb, uxin * ci_xa));
        vx = RESC ? prx * e_x * rz : prx * e_x;
    }
    if (lane == 31 && wid < 3)
        ((float*)&s_bnd[P ^ 1])[wid + 1] = vm[2];
}

// ---------------- forward recursion: 4 warps, alpha in registers, 1 bar/step ----------------
__global__ void __launch_bounds__(128) hmm_forward(const float* __restrict__ seq,
                                                   const float* __restrict__ lscale,
                                                   float* __restrict__ out)
{
    __shared__ float2 s_T[2][4];
    __shared__ float4 s_bnd[2];
    __shared__ float  s_red[4];
    __shared__ int    s_let[LL];

    const int b = blockIdx.x, tid = threadIdx.x, lane = tid & 31, wid = tid >> 5;
    const int j0 = tid * 3;
    const bool l127 = (tid == 127);

    for (int l = tid; l < LL; l += 128) {
        const float* row = seq + ((size_t)b * LL + l) * AA;
        int let = AA;
        #pragma unroll
        for (int a = 0; a < AA; a++)
            if (row[a] > 0.5f) let = a;
        s_let[l] = let * ESTR;
    }

    float w_[3], cfa[3], cfb[3], cma[3], cmb[3], cia[3], cib[3], etm[3], eti[3];
    #pragma unroll
    for (int q = 0; q < 3; q++) {
        const int j = j0 + q;
        w_[q]  = g_w[j];
        cfa[q] = g_cf[MM + j];  cfb[q] = j ? g_cf[j - 1] : 0.f;
        cma[q] = g_cm[MM + j];  cmb[q] = j ? g_cm[j - 1] : 0.f;
        cia[q] = g_ci[MM + j];  cib[q] = j ? g_ci[j - 1] : 0.f;
        etm[q] = g_et[j];       eti[q] = g_et[MM + j];
    }
    const float kw1 = __fdividef(g_cf[95],  g_w[96]);
    const float kw2 = __fdividef(g_cf[191], g_w[192]);
    const float kw3 = __fdividef(g_cf[287], g_w[288]);
    float et_x = 0.f, ci_xa = 0.f, ci_xb = 0.f;
    if (l127) { et_x = g_et[KK - 1]; ci_xa = g_ci[KK - 1]; ci_xb = g_ci[MM - 1]; }

    // precompute constant-W scan multipliers (one dummy W-only scan)
    float WL[5], Wfin;
    {
        float Wv = w_[0] * w_[1] * w_[2];
        #pragma unroll
        for (int k = 0; k < 5; k++) {
            const int o = 1 << k;
            WL[k] = Wv;
            float Wp = __shfl_up_sync(0xffffffffu, Wv, o);
            if (lane >= o) Wv *= Wp;
        }
        Wfin = Wv;   // prefix product over lanes 0..lane
    }
    const float Wexcl = __shfl_up_sync(0xffffffffu, Wfin, 1);
    if (lane == 31) s_red[wid] = Wfin;   // warp W totals
    __syncthreads();
    const float WT1 = s_red[1], WT2 = s_red[2];

    // init: u0 = exp(init) * emission(t=0)
    float um[3], ui[3], ux = 0.f;
    {
        const float* ob = g_eobs + s_let[0];
        #pragma unroll
        for (int q = 0; q < 3; q++) {
            um[q] = g_einit[j0 + q]      * ob[j0 + q];
            ui[q] = g_einit[MM + j0 + q] * ob[MM + j0 + q];
        }
        if (l127) ux = g_einit[KK - 1] * ob[KK - 1];
        if (tid == 0) { ((float*)&s_bnd[0])[0] = 0.f; ((float*)&s_bnd[1])[0] = 0.f; }
        if (lane == 31 && wid < 3) ((float*)&s_bnd[0])[wid + 1] = um[2];
    }
    __syncthreads();

    int pacc = 0;
    float vm[3], vi[3], vx;

    stepfn<true, 0>(um, ui, ux, vm, vi, vx, w_, cfa, cfb, cma, cmb, cia, cib, etm, eti,
                    WL, Wexcl, WT1, WT2, kw1, kw2, kw3, s_T, s_bnd, j0, lane, wid, l127,
                    et_x, ci_xa, ci_xb, g_eobs + s_let[1], pacc);
    for (int t = 2; t < LL; t += 2) {
        stepfn<true, 1>(vm, vi, vx, um, ui, ux, w_, cfa, cfb, cma, cmb, cia, cib, etm, eti,
                        WL, Wexcl, WT1, WT2, kw1, kw2, kw3, s_T, s_bnd, j0, lane, wid, l127,
                        et_x, ci_xa, ci_xb, g_eobs + s_let[t], pacc);
        stepfn<false, 0>(um, ui, ux, vm, vi, vx, w_, cfa, cfb, cma, cmb, cia, cib, etm, eti,
                         WL, Wexcl, WT1, WT2, kw1, kw2, kw3, s_T, s_bnd, j0, lane, wid, l127,
                         et_x, ci_xa, ci_xb, g_eobs + s_let[t + 1], pacc);
    }

    // final: log(sum u) + 2^pacc correction
    float ps = ((vm[0] + vm[1]) + (vm[2] + vx)) + ((vi[0] + vi[1]) + vi[2]);
    #pragma unroll
    for (int o = 16; o; o >>= 1) ps += __shfl_xor_sync(0xffffffffu, ps, o);
    __syncthreads();                 // retire s_red (W totals) before reuse
    if (lane == 0) s_red[wid] = ps;
    __syncthreads();
    if (tid == 0) {
        float Zt = (s_red[0] + s_red[1]) + (s_red[2] + s_red[3]);
        out[b] = lscale[0] * ((float)((double)pacc * 0.6931471805599453) + __logf(Zt));
    }
}

extern "C" void kernel_launch(void* const* d_in, const int* in_sizes, int n_in,
                              void* d_out, int out_size)
{
    const float* pre  = (const float*)d_in[0];
    const float* iseq = (const float*)d_in[1];
    const float* ins  = (const float*)d_in[2];
    const float* del  = (const float*)d_in[3];
    const float* seq  = (const float*)d_in[4];
    const float* ls   = (const float*)d_in[5];
    float* out = (float*)d_out;

    prep_kernel<<<1, 512>>>(ins, del);
    emis_kernel<<<7, 128>>>(pre, iseq);
    hmm_forward<<<BB, 128>>>(seq, ls, out);
}